// round 1
// baseline (speedup 1.0000x reference)
#include <cuda_runtime.h>
#include <math.h>

// Problem constants (fixed by the reference): B=64, N=1024, C=768, heads=8, d=128
#define B_ 64
#define N_ 1024
#define C_ 768
#define H_ 8
#define D_ 128
#define EPSF 1e-8f

// ---------------------------------------------------------------------------
// Scratch (device globals: allocation-free rule)
//   g_xt : x transposed          [B*C, N]   (201 MB)
//   g_k  : k = xt @ qk_w^T, later reused as gelu output   (201 MB)
//   g_v  : v = xt @ v_w^T,  later reused as proj output   (201 MB)
//   g_kt : per-(b,h) 128x128 kernel matrices, pre-scaled  (33 MB)
//   g_wt : transposed weights [3][1024*1024]              (12 MB)
// ---------------------------------------------------------------------------
__device__ float g_xt[(size_t)B_*C_*N_];
__device__ float g_k [(size_t)B_*C_*N_];
__device__ float g_v [(size_t)B_*C_*N_];
__device__ float g_kt[(size_t)B_*H_*D_*D_];
__device__ float g_wt[3][(size_t)N_*N_];
__device__ float g_part[3072];
__device__ float g_norm2;

union F2u { unsigned long long u; float2 f; };

// Packed fp32x2 FMA: 2x FFMA throughput on sm_100a (ptxas never auto-fuses this).
__device__ __forceinline__ unsigned long long fma2(unsigned long long a,
                                                   unsigned long long b,
                                                   unsigned long long c){
  unsigned long long d;
  asm("fma.rn.f32x2 %0, %1, %2, %3;" : "=l"(d) : "l"(a), "l"(b), "l"(c));
  return d;
}
__device__ __forceinline__ unsigned long long pack2(float x){
  unsigned long long d;
  asm("mov.b64 %0, {%1, %1};" : "=l"(d) : "f"(x));
  return d;
}

__device__ __forceinline__ float gelu_exact(float x){
  return 0.5f * x * (1.0f + erff(x * 0.7071067811865475f));
}

// ---------------------------------------------------------------------------
// Shared micro-kernel: 128x128 tile, BK=8, 256 threads, 8x8 per thread.
// acc2[i][j] holds the packed pair (col 2j, col 2j+1) of logical cols
// {tx4..tx4+3, 64+tx4..64+tx4+3}; rows {ty4..ty4+3, 64+ty4..64+ty4+3}.
// ---------------------------------------------------------------------------
__device__ __forceinline__ void mm8(const float (*As)[128], const float (*Bs)[128],
                                    unsigned long long (*acc2)[4], int ty4, int tx4){
#pragma unroll
  for (int kk=0; kk<8; kk++){
    float4 a0 = *(const float4*)(As[kk]+ty4);
    float4 a1 = *(const float4*)(As[kk]+ty4+64);
    ulonglong2 q0 = *(const ulonglong2*)(Bs[kk]+tx4);
    ulonglong2 q1 = *(const ulonglong2*)(Bs[kk]+tx4+64);
    unsigned long long b2[4] = {q0.x, q0.y, q1.x, q1.y};
    float ar[8] = {a0.x,a0.y,a0.z,a0.w,a1.x,a1.y,a1.z,a1.w};
#pragma unroll
    for (int i=0;i<8;i++){
      unsigned long long ap = pack2(ar[i]);
#pragma unroll
      for (int j=0;j<4;j++) acc2[i][j] = fma2(ap, b2[j], acc2[i][j]);
    }
  }
}

// ---------------------------------------------------------------------------
// Generic 32x32 smem transpose: out[z][j][i] = in[z][i][j], i<R, j<S
// grid = (S/32, R/32, Z), block = (32, 8)
// ---------------------------------------------------------------------------
__global__ void k_transpose(const float* __restrict__ in, float* __restrict__ out,
                            int R, int S){
  __shared__ float t[32][33];
  const size_t zo = (size_t)blockIdx.z * R * S;
  const int i0 = blockIdx.y*32, j0 = blockIdx.x*32;
  const float* ip = in + zo;
  float* op = out + zo;
#pragma unroll
  for (int k=threadIdx.y; k<32; k+=8)
    t[k][threadIdx.x] = ip[(size_t)(i0+k)*S + j0 + threadIdx.x];
  __syncthreads();
#pragma unroll
  for (int k=threadIdx.y; k<32; k+=8)
    op[(size_t)(j0+k)*R + i0 + threadIdx.x] = t[threadIdx.x][k];
}

// ---------------------------------------------------------------------------
// K1: k = xt @ qk_w^T (z=0, + ||k||^2 block partials) and v = xt @ v_w^T (z=1)
// grid = (8, 384, 2), block 256
// ---------------------------------------------------------------------------
__global__ void __launch_bounds__(256,2) k_gemm_kv(){
  const int z = blockIdx.z;
  const float* __restrict__ Bw = g_wt[z];
  float* __restrict__ Cm = (z==0) ? g_k : g_v;
  const int n0 = blockIdx.x*128, m0 = blockIdx.y*128;
  __shared__ float As[8][128], Bs[8][128];
  __shared__ float red[8];
  const int tid = threadIdx.x;
  const int ty4 = (tid/16)*4, tx4 = (tid%16)*4;
  const int am = tid>>1, ak = (tid&1)*4;
  const int bk = tid>>5, bn = (tid&31)*4;
  const float* Ap = g_xt + (size_t)(m0+am)*N_ + ak;
  const float* Bp = Bw + (size_t)bk*N_ + n0 + bn;
  unsigned long long acc2[8][4] = {};
  for (int k0=0; k0<N_; k0+=8){
    float4 a = *(const float4*)(Ap + k0);
    float4 b = *(const float4*)(Bp + (size_t)k0*N_);
    __syncthreads();
    As[ak+0][am]=a.x; As[ak+1][am]=a.y; As[ak+2][am]=a.z; As[ak+3][am]=a.w;
    *(float4*)(Bs[bk]+bn) = b;
    __syncthreads();
    mm8(As, Bs, acc2, ty4, tx4);
  }
  float s2 = 0.f;
#pragma unroll
  for (int i=0;i<8;i++){
    const int r = m0 + ty4 + ((i<4) ? i : 60+i);
    float* crow = Cm + (size_t)r*N_ + n0;
    F2u u0,u1,u2,u3; u0.u=acc2[i][0]; u1.u=acc2[i][1]; u2.u=acc2[i][2]; u3.u=acc2[i][3];
    float4 c0 = make_float4(u0.f.x,u0.f.y,u1.f.x,u1.f.y);
    float4 c1 = make_float4(u2.f.x,u2.f.y,u3.f.x,u3.f.y);
    *(float4*)(crow + tx4) = c0;
    *(float4*)(crow + 64 + tx4) = c1;
    s2 += c0.x*c0.x + c0.y*c0.y + c0.z*c0.z + c0.w*c0.w
        + c1.x*c1.x + c1.y*c1.y + c1.z*c1.z + c1.w*c1.w;
  }
  if (z==0){
#pragma unroll
    for (int o=16;o;o>>=1) s2 += __shfl_down_sync(0xffffffffu, s2, o);
    if ((tid&31)==0) red[tid>>5] = s2;
    __syncthreads();
    if (tid==0){
      float t=0.f;
#pragma unroll
      for (int w=0;w<8;w++) t += red[w];
      g_part[blockIdx.y*8 + blockIdx.x] = t;   // deterministic: fixed slot
    }
  }
}

// Deterministic tree reduction of the 3072 block partials -> g_norm2
__global__ void k_reduce(){
  __shared__ float sh[1024];
  const int t = threadIdx.x;
  sh[t] = g_part[t] + g_part[t+1024] + g_part[t+2048];
  __syncthreads();
  for (int o=512; o; o>>=1){
    if (t<o) sh[t] += sh[t+o];
    __syncthreads();
  }
  if (t==0) g_norm2 = sh[0];
}

// ---------------------------------------------------------------------------
// K2: kt[b,h] = (k_bh^T @ v_bh) * scale[h] / (||k||+eps)^2   (both norm divisions folded)
// one block per (b,h): 128x128x768.  grid = 512, block 256
// ---------------------------------------------------------------------------
__global__ void __launch_bounds__(256,2) k_gemm_kt(const float* __restrict__ scale){
  const int bh = blockIdx.x;
  const int b = bh>>3, h = bh&7;
  const size_t base = (size_t)b*C_*N_ + (size_t)h*D_;
  __shared__ float As[8][128], Bs[8][128];
  const int tid = threadIdx.x;
  const int lk = tid>>5, lc = (tid&31)*4;
  const int ty4 = (tid/16)*4, tx4 = (tid%16)*4;
  const float* Ap = g_k + base + (size_t)lk*N_ + lc;
  const float* Bp = g_v + base + (size_t)lk*N_ + lc;
  unsigned long long acc2[8][4] = {};
  for (int c0=0; c0<C_; c0+=8){
    float4 a = *(const float4*)(Ap + (size_t)c0*N_);
    float4 b = *(const float4*)(Bp + (size_t)c0*N_);
    __syncthreads();
    *(float4*)(As[lk]+lc) = a;
    *(float4*)(Bs[lk]+lc) = b;
    __syncthreads();
    mm8(As, Bs, acc2, ty4, tx4);
  }
  const float nrm = sqrtf(g_norm2) + EPSF;
  const float f = scale[h] / (nrm*nrm);
  float* Cp = g_kt + (size_t)bh*D_*D_;
#pragma unroll
  for (int i=0;i<8;i++){
    const int r = ty4 + ((i<4) ? i : 60+i);
    F2u u0,u1,u2,u3; u0.u=acc2[i][0]; u1.u=acc2[i][1]; u2.u=acc2[i][2]; u3.u=acc2[i][3];
    float4 c0 = make_float4(u0.f.x*f,u0.f.y*f,u1.f.x*f,u1.f.y*f);
    float4 c1 = make_float4(u2.f.x*f,u2.f.y*f,u3.f.x*f,u3.f.y*f);
    *(float4*)(Cp + (size_t)r*D_ + tx4) = c0;
    *(float4*)(Cp + (size_t)r*D_ + 64 + tx4) = c1;
  }
}

// ---------------------------------------------------------------------------
// K3: out1[b,h] = xt_bh @ kt_bh, then exact gelu; writes into g_k (k is dead).
// grid = (6, 512), block 256.  K-dim = d = 128.
// ---------------------------------------------------------------------------
__global__ void __launch_bounds__(256,2) k_gemm_out(){
  const int bh = blockIdx.y;
  const int b = bh>>3, h = bh&7;
  const int m0 = blockIdx.x*128;
  __shared__ float As[8][128], Bs[8][128];
  const int tid = threadIdx.x;
  const int am = tid>>1, ak = (tid&1)*4;
  const int bk = tid>>5, bn = (tid&31)*4;
  const int ty4 = (tid/16)*4, tx4 = (tid%16)*4;
  const float* Ap = g_xt + (size_t)(b*C_ + m0 + am)*N_ + h*D_ + ak;
  const float* Bp = g_kt + (size_t)bh*D_*D_ + (size_t)bk*D_ + bn;
  unsigned long long acc2[8][4] = {};
  for (int k0=0; k0<D_; k0+=8){
    float4 a = *(const float4*)(Ap + k0);
    float4 b = *(const float4*)(Bp + (size_t)k0*D_);
    __syncthreads();
    As[ak+0][am]=a.x; As[ak+1][am]=a.y; As[ak+2][am]=a.z; As[ak+3][am]=a.w;
    *(float4*)(Bs[bk]+bn) = b;
    __syncthreads();
    mm8(As, Bs, acc2, ty4, tx4);
  }
#pragma unroll
  for (int i=0;i<8;i++){
    const int r = b*C_ + m0 + ty4 + ((i<4) ? i : 60+i);
    float* crow = g_k + (size_t)r*N_ + h*D_;
    F2u u0,u1,u2,u3; u0.u=acc2[i][0]; u1.u=acc2[i][1]; u2.u=acc2[i][2]; u3.u=acc2[i][3];
    float4 c0 = make_float4(gelu_exact(u0.f.x),gelu_exact(u0.f.y),
                            gelu_exact(u1.f.x),gelu_exact(u1.f.y));
    float4 c1 = make_float4(gelu_exact(u2.f.x),gelu_exact(u2.f.y),
                            gelu_exact(u3.f.x),gelu_exact(u3.f.y));
    *(float4*)(crow + tx4) = c0;
    *(float4*)(crow + 64 + tx4) = c1;
  }
}

// ---------------------------------------------------------------------------
// K4: out2 = gelu_buf @ proj_w^T + pb   (row-major into g_v; final transpose after)
// grid = (8, 384), block 256
// ---------------------------------------------------------------------------
__global__ void __launch_bounds__(256,2) k_gemm_proj(const float* __restrict__ pb){
  const int n0 = blockIdx.x*128, m0 = blockIdx.y*128;
  const float* __restrict__ Bw = g_wt[2];
  __shared__ float As[8][128], Bs[8][128];
  const int tid = threadIdx.x;
  const int am = tid>>1, ak = (tid&1)*4;
  const int bk = tid>>5, bn = (tid&31)*4;
  const int ty4 = (tid/16)*4, tx4 = (tid%16)*4;
  const float* Ap = g_k + (size_t)(m0+am)*N_ + ak;
  const float* Bp = Bw + (size_t)bk*N_ + n0 + bn;
  unsigned long long acc2[8][4] = {};
  for (int k0=0; k0<N_; k0+=8){
    float4 a = *(const float4*)(Ap + k0);
    float4 b = *(const float4*)(Bp + (size_t)k0*N_);
    __syncthreads();
    As[ak+0][am]=a.x; As[ak+1][am]=a.y; As[ak+2][am]=a.z; As[ak+3][am]=a.w;
    *(float4*)(Bs[bk]+bn) = b;
    __syncthreads();
    mm8(As, Bs, acc2, ty4, tx4);
  }
  const float4 pb0 = *(const float4*)(pb + n0 + tx4);
  const float4 pb1 = *(const float4*)(pb + n0 + 64 + tx4);
#pragma unroll
  for (int i=0;i<8;i++){
    const int r = m0 + ty4 + ((i<4) ? i : 60+i);
    float* crow = g_v + (size_t)r*N_ + n0;
    F2u u0,u1,u2,u3; u0.u=acc2[i][0]; u1.u=acc2[i][1]; u2.u=acc2[i][2]; u3.u=acc2[i][3];
    float4 c0 = make_float4(u0.f.x+pb0.x,u0.f.y+pb0.y,u1.f.x+pb0.z,u1.f.y+pb0.w);
    float4 c1 = make_float4(u2.f.x+pb1.x,u2.f.y+pb1.y,u3.f.x+pb1.z,u3.f.y+pb1.w);
    *(float4*)(crow + tx4) = c0;
    *(float4*)(crow + 64 + tx4) = c1;
  }
}

// ---------------------------------------------------------------------------
// Launch: graph-capturable, allocation-free, deterministic.
// ---------------------------------------------------------------------------
extern "C" void kernel_launch(void* const* d_in, const int* in_sizes, int n_in,
                              void* d_out, int out_size){
  const float* x   = (const float*)d_in[0];
  const float* qkw = (const float*)d_in[1];
  const float* vw  = (const float*)d_in[2];
  const float* pw  = (const float*)d_in[3];
  const float* pb  = (const float*)d_in[4];
  const float* sc  = (const float*)d_in[5];
  float* out = (float*)d_out;

  float *p_wt = nullptr, *p_xt = nullptr, *p_v = nullptr;
  cudaGetSymbolAddress((void**)&p_wt, g_wt);
  cudaGetSymbolAddress((void**)&p_xt, g_xt);
  cudaGetSymbolAddress((void**)&p_v,  g_v);

  const dim3 tb(32,8);
  // Weight transposes (so GEMM B-tiles read contiguously) + x -> xt
  k_transpose<<<dim3(32,32,1), tb>>>(qkw, p_wt,               1024, 1024);
  k_transpose<<<dim3(32,32,1), tb>>>(vw,  p_wt + 1048576,     1024, 1024);
  k_transpose<<<dim3(32,32,1), tb>>>(pw,  p_wt + 2097152,     1024, 1024);
  k_transpose<<<dim3(24,32,64), tb>>>(x,  p_xt, 1024, 768);
  // k and v GEMMs (+ norm partials), deterministic norm reduce
  k_gemm_kv<<<dim3(8,384,2), 256>>>();
  k_reduce<<<1,1024>>>();
  // kt, attention output + gelu, projection
  k_gemm_kt<<<512, 256>>>(sc);
  k_gemm_out<<<dim3(6,512), 256>>>();
  k_gemm_proj<<<dim3(8,384), 256>>>(pb);
  // out2 [B,C,N] -> final [B,N,C]
  k_transpose<<<dim3(32,24,64), tb>>>(p_v, out, 768, 1024);
}

// round 4
// speedup vs baseline: 1.7062x; 1.7062x over previous
#include <cuda_runtime.h>
#include <cuda_bf16.h>
#include <math.h>
#include <stdint.h>

// Problem constants: B=64, N=1024, C=768, heads=8, d=128
#define B_ 64
#define N_ 1024
#define C_ 768
#define H_ 8
#define D_ 128
#define EPSF 1e-8f
#define ROWS_ ((size_t)B_*C_)   // 49152

// ---------------------------------------------------------------------------
// Scratch (device globals — allocation-free rule)
// ---------------------------------------------------------------------------
__device__ float g_xt[ROWS_*N_];           // x transposed, fp32 (FFMA out path)
__device__ float g_k [ROWS_*N_];           // k (fp32, feeds kt)
__device__ float g_v [ROWS_*N_];           // v (fp32, feeds kt), later proj output
__device__ float g_kt[(size_t)B_*H_*D_*D_];
__device__ __nv_bfloat16 g_xh[ROWS_*N_];   // xt hi, later gelu hi
__device__ __nv_bfloat16 g_xl[ROWS_*N_];   // xt lo, later gelu lo
__device__ __nv_bfloat16 g_wh[3][(size_t)N_*N_];
__device__ __nv_bfloat16 g_wl[3][(size_t)N_*N_];
__device__ float g_part[3072];
__device__ float g_norm2;

// ---------------------------------------------------------------------------
// Helpers
// ---------------------------------------------------------------------------
__device__ __forceinline__ uint32_t smem_u32(const void* p){
  uint32_t a;
  asm("{ .reg .u64 t; cvta.to.shared.u64 t, %1; cvt.u32.u64 %0, t; }" : "=r"(a) : "l"(p));
  return a;
}
// bf16 hi/lo split of two floats -> packed bf16x2 regs (mem order [x,y])
__device__ __forceinline__ void split2(float fx, float fy, uint32_t& hi, uint32_t& lo){
  uint32_t h;
  asm("cvt.rn.bf16x2.f32 %0, %1, %2;" : "=r"(h) : "f"(fy), "f"(fx));
  float hx = __uint_as_float(h << 16);
  float hy = __uint_as_float(h & 0xffff0000u);
  float lx = fx - hx, ly = fy - hy;
  asm("cvt.rn.bf16x2.f32 %0, %1, %2;" : "=r"(lo) : "f"(ly), "f"(lx));
  hi = h;
}
__device__ __forceinline__ float gelu_exact(float x){
  return 0.5f * x * (1.0f + erff(x * 0.7071067811865475f));
}

#define CP_ASYNC16(s, g) \
  asm volatile("cp.async.cg.shared.global [%0], [%1], 16;" :: "r"(s), "l"(g) : "memory")
#define CP_COMMIT() asm volatile("cp.async.commit_group;" ::: "memory")
#define CP_WAIT1()  asm volatile("cp.async.wait_group 1;" ::: "memory")

__device__ __forceinline__ void ldmx4(uint32_t* r, uint32_t addr){
  asm volatile("ldmatrix.sync.aligned.m8n8.x4.shared.b16 {%0,%1,%2,%3}, [%4];"
    : "=r"(r[0]), "=r"(r[1]), "=r"(r[2]), "=r"(r[3]) : "r"(addr));
}
__device__ __forceinline__ void mma16816(float* c, const uint32_t* a, const uint32_t* b){
  asm volatile("mma.sync.aligned.m16n8k16.row.col.f32.bf16.bf16.f32 "
    "{%0,%1,%2,%3},{%4,%5,%6,%7},{%8,%9},{%0,%1,%2,%3};"
    : "+f"(c[0]), "+f"(c[1]), "+f"(c[2]), "+f"(c[3])
    : "r"(a[0]), "r"(a[1]), "r"(a[2]), "r"(a[3]), "r"(b[0]), "r"(b[1]));
}

// ===========================================================================
// k_split: fp32 -> bf16 hi/lo (weights only, 2MB each)
// ===========================================================================
__global__ void k_split(const float4* __restrict__ in, uint2* __restrict__ hi,
                        uint2* __restrict__ lo, int n4){
  int i = blockIdx.x * blockDim.x + threadIdx.x;
  if (i >= n4) return;
  float4 v = in[i];
  uint32_t h0,l0,h1,l1;
  split2(v.x, v.y, h0, l0);
  split2(v.z, v.w, h1, l1);
  hi[i] = make_uint2(h0, h1);
  lo[i] = make_uint2(l0, l1);
}

// ===========================================================================
// HMMA GEMM: C[m0:+128, n0:+128] = A @ B^T, K=1024, bf16 hi/lo 3-term split.
// A*, B* bf16 row-major [rows,1024]. Warp grid 2x4, warp tile 64x32.
// mode 0: + ||C||^2 partials (k); 1: plain (v); 2: += bias (proj)
// grid (8, 384), block 256, 3-stage cp.async pipeline, 120KB dynamic smem.
// ===========================================================================
#define KC 32
#define RSB 80                      // smem row stride bytes (conflict-light)
#define TILE_SB (128*RSB)           // 10240 B per tile
#define STAGE_B (4*TILE_SB)         // Ah,Al,Bh,Bl
#define NSTAGE 3
#define GSMEM (NSTAGE*STAGE_B)      // 122880 B

__global__ void __launch_bounds__(256,1)
k_tgemm_mma(const __nv_bfloat16* __restrict__ Ah, const __nv_bfloat16* __restrict__ Al,
            const __nv_bfloat16* __restrict__ Bh, const __nv_bfloat16* __restrict__ Bl,
            float* __restrict__ Cm, const float* __restrict__ bias, int mode){
  extern __shared__ __align__(128) char smem[];
  __shared__ float red[8];
  const uint32_t sb = smem_u32(smem);
  const int tid = threadIdx.x;
  const int n0 = blockIdx.x * 128, m0 = blockIdx.y * 128;

  // cp.async mapping: 4 tiles x 64 threads; 8 segs of 16B per thread
  const int t64  = tid & 63;
  const int tile = tid >> 6;                 // 0:Ah 1:Al 2:Bh 3:Bl
  const __nv_bfloat16* gsrc;
  if      (tile == 0) gsrc = Ah + (size_t)m0 * N_;
  else if (tile == 1) gsrc = Al + (size_t)m0 * N_;
  else if (tile == 2) gsrc = Bh + (size_t)n0 * N_;
  else                gsrc = Bl + (size_t)n0 * N_;

  auto issue = [&](int ch, int stage){
    const int k0 = ch * KC;
    const uint32_t sbase = sb + stage * STAGE_B + tile * TILE_SB;
#pragma unroll
    for (int j = 0; j < 8; j++){
      const int seg = t64 + 64 * j;
      const int row = seg >> 2, s4 = seg & 3;
      CP_ASYNC16(sbase + row * RSB + s4 * 16,
                 (const char*)(gsrc + (size_t)row * N_ + k0) + s4 * 16);
    }
    CP_COMMIT();
  };

  issue(0, 0);
  issue(1, 1);

  const int wid = tid >> 5, lane = tid & 31;
  const int wm = (wid >> 2) * 64, wn = (wid & 3) * 32;
  // ldmatrix lane addressing
  const int a_row = lane % 16, a_k8 = (lane >> 4) * 8;          // A
  const int b_row = (lane & 7) + ((lane >> 4) * 8);             // B
  const int b_k8  = ((lane >> 3) & 1) * 8;

  float acc[4][4][4] = {};

  for (int ch = 0; ch < 32; ch++){
    CP_WAIT1();
    __syncthreads();
    const int ch2 = ch + 2;
    if (ch2 < 32) issue(ch2, ch2 % 3);
    else CP_COMMIT();   // keep group count uniform for CP_WAIT1

    const uint32_t st = sb + (ch % 3) * STAGE_B;
    const uint32_t aH = st,             aL = st + TILE_SB;
    const uint32_t bH = st + 2*TILE_SB, bL = st + 3*TILE_SB;

#pragma unroll
    for (int kk = 0; kk < 2; kk++){
      uint32_t ah[4][4], al[4][4], bh[4][2], bl[4][2];
      const int kc = kk * 32 + a_k8 * 2;   // byte col offset for A lanes
#pragma unroll
      for (int mi = 0; mi < 4; mi++){
        const uint32_t ro = (uint32_t)(wm + mi*16 + a_row) * RSB + kc;
        ldmx4(ah[mi], aH + ro);
        ldmx4(al[mi], aL + ro);
      }
#pragma unroll
      for (int nh = 0; nh < 2; nh++){
        const uint32_t ro = (uint32_t)(wn + nh*16 + b_row) * RSB + kk*32 + b_k8*2;
        uint32_t r[4];
        ldmx4(r, bH + ro);
        bh[nh*2+0][0]=r[0]; bh[nh*2+0][1]=r[1]; bh[nh*2+1][0]=r[2]; bh[nh*2+1][1]=r[3];
        ldmx4(r, bL + ro);
        bl[nh*2+0][0]=r[0]; bl[nh*2+0][1]=r[1]; bl[nh*2+1][0]=r[2]; bl[nh*2+1][1]=r[3];
      }
#pragma unroll
      for (int mi = 0; mi < 4; mi++)
#pragma unroll
        for (int ni = 0; ni < 4; ni++){
          mma16816(acc[mi][ni], ah[mi], bh[ni]);
          mma16816(acc[mi][ni], ah[mi], bl[ni]);
          mma16816(acc[mi][ni], al[mi], bh[ni]);
        }
    }
  }

  // Epilogue
  const int tr = lane >> 2, tc = (lane & 3) * 2;
  float s2 = 0.f;
#pragma unroll
  for (int mi = 0; mi < 4; mi++){
#pragma unroll
    for (int ni = 0; ni < 4; ni++){
      float* a = acc[mi][ni];
      const int col = n0 + wn + ni*8 + tc;
      if (mode == 2){
        const float2 bv = *(const float2*)(bias + col);
        a[0] += bv.x; a[1] += bv.y; a[2] += bv.x; a[3] += bv.y;
      } else if (mode == 0){
        s2 += a[0]*a[0] + a[1]*a[1] + a[2]*a[2] + a[3]*a[3];
      }
      const int r0 = m0 + wm + mi*16 + tr;
      *(float2*)(Cm + (size_t)r0 * N_ + col)     = make_float2(a[0], a[1]);
      *(float2*)(Cm + (size_t)(r0+8) * N_ + col) = make_float2(a[2], a[3]);
    }
  }
  if (mode == 0){
#pragma unroll
    for (int o = 16; o; o >>= 1) s2 += __shfl_down_sync(0xffffffffu, s2, o);
    if (lane == 0) red[wid] = s2;
    __syncthreads();
    if (tid == 0){
      float t = 0.f;
#pragma unroll
      for (int w = 0; w < 8; w++) t += red[w];
      g_part[blockIdx.y * 8 + blockIdx.x] = t;
    }
  }
}

// ===========================================================================
// FFMA path: transposes, reduce, per-head GEMMs
// ===========================================================================
union F2u { unsigned long long u; float2 f; };
__device__ __forceinline__ unsigned long long fma2(unsigned long long a,
                                                   unsigned long long b,
                                                   unsigned long long c){
  unsigned long long d;
  asm("fma.rn.f32x2 %0, %1, %2, %3;" : "=l"(d) : "l"(a), "l"(b), "l"(c));
  return d;
}
__device__ __forceinline__ unsigned long long pack2(float x){
  unsigned long long d;
  asm("mov.b64 %0, {%1, %1};" : "=l"(d) : "f"(x));
  return d;
}

__device__ __forceinline__ void mm8(const float (*As)[128], const float (*Bs)[128],
                                    unsigned long long (*acc2)[4], int ty4, int tx4){
#pragma unroll
  for (int kk=0; kk<8; kk++){
    float4 a0 = *(const float4*)(As[kk]+ty4);
    float4 a1 = *(const float4*)(As[kk]+ty4+64);
    ulonglong2 q0 = *(const ulonglong2*)(Bs[kk]+tx4);
    ulonglong2 q1 = *(const ulonglong2*)(Bs[kk]+tx4+64);
    unsigned long long b2[4] = {q0.x, q0.y, q1.x, q1.y};
    float ar[8] = {a0.x,a0.y,a0.z,a0.w,a1.x,a1.y,a1.z,a1.w};
#pragma unroll
    for (int i=0;i<8;i++){
      unsigned long long ap = pack2(ar[i]);
#pragma unroll
      for (int j=0;j<4;j++) acc2[i][j] = fma2(ap, b2[j], acc2[i][j]);
    }
  }
}

// x transpose fused with bf16 hi/lo split: writes fp32 xt + xh + xl
__global__ void k_transpose_x(const float* __restrict__ in){
  __shared__ float t[32][33];
  const size_t zo = (size_t)blockIdx.z * 768 * 1024;
  const int i0 = blockIdx.y*32, j0 = blockIdx.x*32;
  const float* ip = in + zo;
#pragma unroll
  for (int k=threadIdx.y; k<32; k+=8)
    t[k][threadIdx.x] = ip[(size_t)(i0+k)*768 + j0 + threadIdx.x];
  __syncthreads();
#pragma unroll
  for (int k=threadIdx.y; k<32; k+=8){
    const size_t o = zo + (size_t)(j0+k)*1024 + i0 + threadIdx.x;
    const float v = t[threadIdx.x][k];
    g_xt[o] = v;
    uint32_t h;
    asm("cvt.rn.bf16x2.f32 %0, %1, %1;" : "=r"(h) : "f"(v));
    const float hv = __uint_as_float(h << 16);
    g_xh[o] = __ushort_as_bfloat16((unsigned short)(h & 0xffffu));
    float lv = v - hv;
    uint32_t l;
    asm("cvt.rn.bf16x2.f32 %0, %1, %1;" : "=r"(l) : "f"(lv));
    g_xl[o] = __ushort_as_bfloat16((unsigned short)(l & 0xffffu));
  }
}

__global__ void k_transpose(const float* __restrict__ in, float* __restrict__ out,
                            int R, int S){
  __shared__ float t[32][33];
  const size_t zo = (size_t)blockIdx.z * R * S;
  const int i0 = blockIdx.y*32, j0 = blockIdx.x*32;
  const float* ip = in + zo;
  float* op = out + zo;
#pragma unroll
  for (int k=threadIdx.y; k<32; k+=8)
    t[k][threadIdx.x] = ip[(size_t)(i0+k)*S + j0 + threadIdx.x];
  __syncthreads();
#pragma unroll
  for (int k=threadIdx.y; k<32; k+=8)
    op[(size_t)(j0+k)*R + i0 + threadIdx.x] = t[threadIdx.x][k];
}

__global__ void k_reduce(){
  __shared__ float sh[1024];
  const int t = threadIdx.x;
  sh[t] = g_part[t] + g_part[t+1024] + g_part[t+2048];
  __syncthreads();
  for (int o=512; o; o>>=1){
    if (t<o) sh[t] += sh[t+o];
    __syncthreads();
  }
  if (t==0) g_norm2 = sh[0];
}

__global__ void __launch_bounds__(256,2) k_gemm_kt(const float* __restrict__ scale){
  const int bh = blockIdx.x;
  const int b = bh>>3, h = bh&7;
  const size_t base = (size_t)b*C_*N_ + (size_t)h*D_;
  __shared__ float As[8][128], Bs[8][128];
  const int tid = threadIdx.x;
  const int lk = tid>>5, lc = (tid&31)*4;
  const int ty4 = (tid/16)*4, tx4 = (tid%16)*4;
  const float* Ap = g_k + base + (size_t)lk*N_ + lc;
  const float* Bp = g_v + base + (size_t)lk*N_ + lc;
  unsigned long long acc2[8][4] = {};
  for (int c0=0; c0<C_; c0+=8){
    float4 a = *(const float4*)(Ap + (size_t)c0*N_);
    float4 b = *(const float4*)(Bp + (size_t)c0*N_);
    __syncthreads();
    *(float4*)(As[lk]+lc) = a;
    *(float4*)(Bs[lk]+lc) = b;
    __syncthreads();
    mm8(As, Bs, acc2, ty4, tx4);
  }
  const float nrm = sqrtf(g_norm2) + EPSF;
  const float f = scale[h] / (nrm*nrm);
  float* Cp = g_kt + (size_t)bh*D_*D_;
#pragma unroll
  for (int i=0;i<8;i++){
    const int r = ty4 + ((i<4) ? i : 60+i);
    F2u u0,u1,u2,u3; u0.u=acc2[i][0]; u1.u=acc2[i][1]; u2.u=acc2[i][2]; u3.u=acc2[i][3];
    float4 c0 = make_float4(u0.f.x*f,u0.f.y*f,u1.f.x*f,u1.f.y*f);
    float4 c1 = make_float4(u2.f.x*f,u2.f.y*f,u3.f.x*f,u3.f.y*f);
    *(float4*)(Cp + (size_t)r*D_ + tx4) = c0;
    *(float4*)(Cp + (size_t)r*D_ + 64 + tx4) = c1;
  }
}

// out1 = xt @ kt, exact gelu, emit bf16 hi/lo (feeds proj HMMA GEMM)
__global__ void __launch_bounds__(256,2) k_gemm_out(){
  const int bh = blockIdx.y;
  const int b = bh>>3, h = bh&7;
  const int m0 = blockIdx.x*128;
  __shared__ float As[8][128], Bs[8][128];
  const int tid = threadIdx.x;
  const int am = tid>>1, ak = (tid&1)*4;
  const int bk = tid>>5, bn = (tid&31)*4;
  const int ty4 = (tid/16)*4, tx4 = (tid%16)*4;
  const float* Ap = g_xt + (size_t)(b*C_ + m0 + am)*N_ + h*D_ + ak;
  const float* Bp = g_kt + (size_t)bh*D_*D_ + (size_t)bk*D_ + bn;
  unsigned long long acc2[8][4] = {};
  for (int k0=0; k0<D_; k0+=8){
    float4 a = *(const float4*)(Ap + k0);
    float4 b = *(const float4*)(Bp + (size_t)k0*D_);
    __syncthreads();
    As[ak+0][am]=a.x; As[ak+1][am]=a.y; As[ak+2][am]=a.z; As[ak+3][am]=a.w;
    *(float4*)(Bs[bk]+bn) = b;
    __syncthreads();
    mm8(As, Bs, acc2, ty4, tx4);
  }
#pragma unroll
  for (int i=0;i<8;i++){
    const size_t r = (size_t)(b*C_ + m0 + ty4 + ((i<4) ? i : 60+i)) * N_ + h*D_;
    F2u u0,u1,u2,u3; u0.u=acc2[i][0]; u1.u=acc2[i][1]; u2.u=acc2[i][2]; u3.u=acc2[i][3];
    float g0 = gelu_exact(u0.f.x), g1 = gelu_exact(u0.f.y);
    float g2 = gelu_exact(u1.f.x), g3 = gelu_exact(u1.f.y);
    float g4 = gelu_exact(u2.f.x), g5 = gelu_exact(u2.f.y);
    float g6 = gelu_exact(u3.f.x), g7 = gelu_exact(u3.f.y);
    uint32_t h0,l0,h1,l1;
    split2(g0,g1,h0,l0); split2(g2,g3,h1,l1);
    *(uint2*)&g_xh[r + tx4] = make_uint2(h0,h1);
    *(uint2*)&g_xl[r + tx4] = make_uint2(l0,l1);
    split2(g4,g5,h0,l0); split2(g6,g7,h1,l1);
    *(uint2*)&g_xh[r + 64 + tx4] = make_uint2(h0,h1);
    *(uint2*)&g_xl[r + 64 + tx4] = make_uint2(l0,l1);
  }
}

// ---------------------------------------------------------------------------
// Launch: graph-capturable, allocation-free, deterministic.
// ---------------------------------------------------------------------------
extern "C" void kernel_launch(void* const* d_in, const int* in_sizes, int n_in,
                              void* d_out, int out_size){
  const float* x   = (const float*)d_in[0];
  const float* qkw = (const float*)d_in[1];
  const float* vw  = (const float*)d_in[2];
  const float* pw  = (const float*)d_in[3];
  const float* pb  = (const float*)d_in[4];
  const float* sc  = (const float*)d_in[5];
  float* out = (float*)d_out;

  float *p_k=nullptr, *p_v=nullptr;
  __nv_bfloat16 *p_xh=nullptr, *p_xl=nullptr, *p_wh=nullptr, *p_wl=nullptr;
  cudaGetSymbolAddress((void**)&p_k,  g_k);
  cudaGetSymbolAddress((void**)&p_v,  g_v);
  cudaGetSymbolAddress((void**)&p_xh, g_xh);
  cudaGetSymbolAddress((void**)&p_xl, g_xl);
  cudaGetSymbolAddress((void**)&p_wh, g_wh);
  cudaGetSymbolAddress((void**)&p_wl, g_wl);

  cudaFuncSetAttribute(k_tgemm_mma, cudaFuncAttributeMaxDynamicSharedMemorySize, GSMEM);

  const dim3 tb(32,8);
  const size_t W2 = (size_t)N_*N_;

  // x -> xt (fp32 + bf16 hi/lo fused); weight splits (2MB each)
  k_transpose_x<<<dim3(24,32,64), tb>>>(x);
  k_split<<<1024, 256>>>((const float4*)qkw, (uint2*)(p_wh),      (uint2*)(p_wl),      (int)(W2/4));
  k_split<<<1024, 256>>>((const float4*)vw,  (uint2*)(p_wh+W2),   (uint2*)(p_wl+W2),   (int)(W2/4));
  k_split<<<1024, 256>>>((const float4*)pw,  (uint2*)(p_wh+2*W2), (uint2*)(p_wl+2*W2), (int)(W2/4));

  // k = xt @ qk_w^T (+ norm partials), v = xt @ v_w^T  (HMMA)
  k_tgemm_mma<<<dim3(8,384), 256, GSMEM>>>(p_xh, p_xl, p_wh,      p_wl,      p_k, nullptr, 0);
  k_tgemm_mma<<<dim3(8,384), 256, GSMEM>>>(p_xh, p_xl, p_wh+W2,   p_wl+W2,   p_v, nullptr, 1);
  k_reduce<<<1,1024>>>();

  // per-head small GEMMs (FFMA); gelu emits bf16 hi/lo into g_xh/g_xl
  k_gemm_kt<<<512, 256>>>(sc);
  k_gemm_out<<<dim3(6,512), 256>>>();

  // proj = gelu @ proj_w^T + pb  (HMMA, bias fused)
  k_tgemm_mma<<<dim3(8,384), 256, GSMEM>>>(p_xh, p_xl, p_wh+2*W2, p_wl+2*W2, p_v, pb, 2);

  // [B,C,N] -> [B,N,C]
  k_transpose<<<dim3(32,24,64), tb>>>(p_v, out, 768, 1024);
}

// round 6
// speedup vs baseline: 1.8476x; 1.0828x over previous
#include <cuda_runtime.h>
#include <cuda_bf16.h>
#include <math.h>
#include <stdint.h>

// Problem constants: B=64, N=1024, C=768, heads=8, d=128
#define B_ 64
#define N_ 1024
#define C_ 768
#define H_ 8
#define D_ 128
#define EPSF 1e-8f
#define ROWS_ ((size_t)B_*C_)   // 49152

// ---------------------------------------------------------------------------
// Scratch (device globals — allocation-free rule)
// ---------------------------------------------------------------------------
__device__ __nv_bfloat16 g_xh[ROWS_*N_];   // xt hi, later gelu hi (in-place)
__device__ __nv_bfloat16 g_xl[ROWS_*N_];   // xt lo, later gelu lo
__device__ __nv_bfloat16 g_kTh[(size_t)B_*N_*C_];  // kT [b][n][c] hi
__device__ __nv_bfloat16 g_kTl[(size_t)B_*N_*C_];
__device__ __nv_bfloat16 g_vTh[(size_t)B_*N_*C_];
__device__ __nv_bfloat16 g_vTl[(size_t)B_*N_*C_];
__device__ __nv_bfloat16 g_kth[(size_t)B_*H_*D_*D_];  // ktT [bh][m][n] hi
__device__ __nv_bfloat16 g_ktl[(size_t)B_*H_*D_*D_];
__device__ __nv_bfloat16 g_wh[3][(size_t)N_*N_];
__device__ __nv_bfloat16 g_wl[3][(size_t)N_*N_];
__device__ float g_part[3072];
__device__ float g_norm2;

// ---------------------------------------------------------------------------
// Helpers
// ---------------------------------------------------------------------------
__device__ __forceinline__ uint32_t smem_u32(const void* p){
  uint32_t a;
  asm("{ .reg .u64 t; cvta.to.shared.u64 t, %1; cvt.u32.u64 %0, t; }" : "=r"(a) : "l"(p));
  return a;
}
// bf16 hi/lo split of two floats -> packed bf16x2 regs (mem order [x,y])
__device__ __forceinline__ void split2(float fx, float fy, uint32_t& hi, uint32_t& lo){
  uint32_t h;
  asm("cvt.rn.bf16x2.f32 %0, %1, %2;" : "=r"(h) : "f"(fy), "f"(fx));
  float hx = __uint_as_float(h << 16);
  float hy = __uint_as_float(h & 0xffff0000u);
  float lx = fx - hx, ly = fy - hy;
  asm("cvt.rn.bf16x2.f32 %0, %1, %2;" : "=r"(lo) : "f"(ly), "f"(lx));
  hi = h;
}
__device__ __forceinline__ float gelu_exact(float x){
  return 0.5f * x * (1.0f + erff(x * 0.7071067811865475f));
}

#define CP_ASYNC16(s, g) \
  asm volatile("cp.async.cg.shared.global [%0], [%1], 16;" :: "r"(s), "l"(g) : "memory")
#define CP_COMMIT() asm volatile("cp.async.commit_group;" ::: "memory")
#define CP_WAIT1()  asm volatile("cp.async.wait_group 1;" ::: "memory")
#define CP_WAIT0()  asm volatile("cp.async.wait_group 0;" ::: "memory")

__device__ __forceinline__ void ldmx4(uint32_t* r, uint32_t addr){
  asm volatile("ldmatrix.sync.aligned.m8n8.x4.shared.b16 {%0,%1,%2,%3}, [%4];"
    : "=r"(r[0]), "=r"(r[1]), "=r"(r[2]), "=r"(r[3]) : "r"(addr));
}
__device__ __forceinline__ void mma16816(float* c, const uint32_t* a, const uint32_t* b){
  asm volatile("mma.sync.aligned.m16n8k16.row.col.f32.bf16.bf16.f32 "
    "{%0,%1,%2,%3},{%4,%5,%6,%7},{%8,%9},{%0,%1,%2,%3};"
    : "+f"(c[0]), "+f"(c[1]), "+f"(c[2]), "+f"(c[3])
    : "r"(a[0]), "r"(a[1]), "r"(a[2]), "r"(a[3]), "r"(b[0]), "r"(b[1]));
}

// ===========================================================================
// k_split: fp32 -> bf16 hi/lo (weights only, 2MB each)
// ===========================================================================
__global__ void k_split(const float4* __restrict__ in, uint2* __restrict__ hi,
                        uint2* __restrict__ lo, int n4){
  int i = blockIdx.x * blockDim.x + threadIdx.x;
  if (i >= n4) return;
  float4 v = in[i];
  uint32_t h0,l0,h1,l1;
  split2(v.x, v.y, h0, l0);
  split2(v.z, v.w, h1, l1);
  hi[i] = make_uint2(h0, h1);
  lo[i] = make_uint2(l0, l1);
}

// ===========================================================================
// Shared HMMA mainloop: C128x128 += A @ B^T over nch*32 K, 3-term bf16 split.
// A*,B* bf16 row-major (128 rows each, given leading dims). 8 warps 2x4.
// acc is [16][4]: acc[4*mi+ni]
// ===========================================================================
#define KC 32
#define RSB 80
#define TILE_SB (128*RSB)           // 10240 B
#define STAGE_B (4*TILE_SB)         // Ah,Al,Bh,Bl
#define GSMEM (3*STAGE_B)           // 122880 B

__device__ __forceinline__ void gemm_main(
    uint32_t sb, int tid,
    const __nv_bfloat16* __restrict__ Ah, const __nv_bfloat16* __restrict__ Al, int lda,
    const __nv_bfloat16* __restrict__ Bh, const __nv_bfloat16* __restrict__ Bl, int ldb,
    int nch, float (*acc)[4]){
  const int t64  = tid & 63;
  const int tile = tid >> 6;                 // 0:Ah 1:Al 2:Bh 3:Bl
  const __nv_bfloat16* gsrc; int ld;
  if      (tile == 0){ gsrc = Ah; ld = lda; }
  else if (tile == 1){ gsrc = Al; ld = lda; }
  else if (tile == 2){ gsrc = Bh; ld = ldb; }
  else               { gsrc = Bl; ld = ldb; }

  auto issue = [&](int ch, int stage){
    const int k0 = ch * KC;
    const uint32_t sbase = sb + stage * STAGE_B + tile * TILE_SB;
#pragma unroll
    for (int j = 0; j < 8; j++){
      const int seg = t64 + 64 * j;
      const int row = seg >> 2, s4 = seg & 3;
      CP_ASYNC16(sbase + row * RSB + s4 * 16,
                 (const char*)(gsrc + (size_t)row * ld + k0) + s4 * 16);
    }
    CP_COMMIT();
  };

  issue(0, 0);
  issue(1, 1);

  const int wid = tid >> 5, lane = tid & 31;
  const int wm = (wid >> 2) * 64, wn = (wid & 3) * 32;
  const int a_row = lane % 16, a_k8 = (lane >> 4) * 8;
  const int b_row = (lane & 7) + ((lane >> 4) * 8);
  const int b_k8  = ((lane >> 3) & 1) * 8;

  for (int ch = 0; ch < nch; ch++){
    CP_WAIT1();
    __syncthreads();
    if (ch + 2 < nch) issue(ch + 2, (ch + 2) % 3);
    else CP_COMMIT();   // keep group count uniform for CP_WAIT1

    const uint32_t st = sb + (ch % 3) * STAGE_B;
    const uint32_t aH = st,             aL = st + TILE_SB;
    const uint32_t bH = st + 2*TILE_SB, bL = st + 3*TILE_SB;

#pragma unroll
    for (int kk = 0; kk < 2; kk++){
      uint32_t ah[4][4], al[4][4], bh[4][2], bl[4][2];
      const int kc = kk * 32 + a_k8 * 2;
#pragma unroll
      for (int mi = 0; mi < 4; mi++){
        const uint32_t ro = (uint32_t)(wm + mi*16 + a_row) * RSB + kc;
        ldmx4(ah[mi], aH + ro);
        ldmx4(al[mi], aL + ro);
      }
#pragma unroll
      for (int nh = 0; nh < 2; nh++){
        const uint32_t ro = (uint32_t)(wn + nh*16 + b_row) * RSB + kk*32 + b_k8*2;
        uint32_t r[4];
        ldmx4(r, bH + ro);
        bh[nh*2+0][0]=r[0]; bh[nh*2+0][1]=r[1]; bh[nh*2+1][0]=r[2]; bh[nh*2+1][1]=r[3];
        ldmx4(r, bL + ro);
        bl[nh*2+0][0]=r[0]; bl[nh*2+0][1]=r[1]; bl[nh*2+1][0]=r[2]; bl[nh*2+1][1]=r[3];
      }
#pragma unroll
      for (int mi = 0; mi < 4; mi++)
#pragma unroll
        for (int ni = 0; ni < 4; ni++){
          mma16816(acc[4*mi+ni], ah[mi], bh[ni]);
          mma16816(acc[4*mi+ni], ah[mi], bl[ni]);
          mma16816(acc[4*mi+ni], al[mi], bh[ni]);
        }
    }
  }
  CP_WAIT0();
  __syncthreads();   // stages free for epilogue reuse
}

// Transposed bf16 hi/lo epilogue via fp32 smem bounce.
// dsth/dstl pre-offset so element (j = gemm_n, m = gemm_m) goes to j*ldd + m.
#define TS 130
__device__ __forceinline__ void epi_T_bf16(
    float (*acc)[4], char* smem, int tid, float f,
    __nv_bfloat16* dsth, __nv_bfloat16* dstl, int ldd){
  float* T = (float*)smem;
  const int wid = tid >> 5, lane = tid & 31;
  const int wm = (wid >> 2) * 64, wn = (wid & 3) * 32;
  const int tr = lane >> 2, tc = (lane & 3) * 2;
#pragma unroll
  for (int mi = 0; mi < 4; mi++)
#pragma unroll
    for (int ni = 0; ni < 4; ni++){
      float* a = acc[4*mi+ni];
      const int r = wm + mi*16 + tr, c = wn + ni*8 + tc;
      T[r*TS + c]     = a[0]*f; T[r*TS + c + 1]     = a[1]*f;
      T[(r+8)*TS + c] = a[2]*f; T[(r+8)*TS + c + 1] = a[3]*f;
    }
  __syncthreads();
#pragma unroll
  for (int it = 0; it < 4; it++){
    const int j = it*32 + (tid >> 3);
    const int mbase = (tid & 7) * 2;
#pragma unroll
    for (int p = 0; p < 8; p++){
      const int m = mbase + p*16;
      float f0 = T[m*TS + j], f1 = T[(m+1)*TS + j];
      uint32_t h, l; split2(f0, f1, h, l);
      *(uint32_t*)(dsth + (size_t)j*ldd + m) = h;
      *(uint32_t*)(dstl + (size_t)j*ldd + m) = l;
    }
  }
  __syncthreads();
}

// ===========================================================================
// kv GEMM: C = xt @ W^T -> write transposed bf16 hi/lo (+ norm partials)
// grid (8, 384)
// ===========================================================================
__global__ void __launch_bounds__(256,1)
k_gemm_kv(const __nv_bfloat16* __restrict__ Wh, const __nv_bfloat16* __restrict__ Wl,
          __nv_bfloat16* __restrict__ dsth, __nv_bfloat16* __restrict__ dstl,
          int with_norm){
  extern __shared__ __align__(128) char smem[];
  __shared__ float red[8];
  const uint32_t sb = smem_u32(smem);
  const int tid = threadIdx.x;
  const int n0 = blockIdx.x * 128, m0 = blockIdx.y * 128;
  float acc[16][4] = {};
  gemm_main(sb, tid, g_xh + (size_t)m0*N_, g_xl + (size_t)m0*N_, N_,
            Wh + (size_t)n0*N_, Wl + (size_t)n0*N_, N_, 32, acc);
  if (with_norm){
    float s2 = 0.f;
#pragma unroll
    for (int q = 0; q < 16; q++)
#pragma unroll
      for (int e = 0; e < 4; e++) s2 += acc[q][e]*acc[q][e];
#pragma unroll
    for (int o = 16; o; o >>= 1) s2 += __shfl_down_sync(0xffffffffu, s2, o);
    if ((tid & 31) == 0) red[tid >> 5] = s2;
    __syncthreads();
    if (tid == 0){
      float t = 0.f;
#pragma unroll
      for (int w = 0; w < 8; w++) t += red[w];
      g_part[blockIdx.y * 8 + blockIdx.x] = t;
    }
  }
  const int b = m0 / C_, c0 = m0 % C_;
  const size_t off = ((size_t)b*N_ + n0) * C_ + c0;
  epi_T_bf16(acc, smem, tid, 1.f, dsth + off, dstl + off, C_);
}

__global__ void k_reduce(){
  __shared__ float sh[1024];
  const int t = threadIdx.x;
  sh[t] = g_part[t] + g_part[t+1024] + g_part[t+2048];
  __syncthreads();
  for (int o = 512; o; o >>= 1){
    if (t < o) sh[t] += sh[t+o];
    __syncthreads();
  }
  if (t == 0) g_norm2 = sh[0];
}

// ===========================================================================
// kt GEMM: kt[n][m] = sum_c kT[n][c] * vT[m][c]; scaled; store ktT[m][n].
// grid 512 (bh)
// ===========================================================================
__global__ void __launch_bounds__(256,1)
k_gemm_kt(const float* __restrict__ scale){
  extern __shared__ __align__(128) char smem[];
  const uint32_t sb = smem_u32(smem);
  const int tid = threadIdx.x;
  const int bh = blockIdx.x, b = bh >> 3, h = bh & 7;
  const size_t base = ((size_t)b*N_ + h*D_) * C_;
  float acc[16][4] = {};
  gemm_main(sb, tid, g_kTh + base, g_kTl + base, C_,
            g_vTh + base, g_vTl + base, C_, 24, acc);
  const float nrm = sqrtf(g_norm2) + EPSF;
  const float f = scale[h] / (nrm*nrm);
  epi_T_bf16(acc, smem, tid, f,
             g_kth + (size_t)bh*D_*D_, g_ktl + (size_t)bh*D_*D_, D_);
}

// ===========================================================================
// out GEMM: out1 = q @ kt (K=128) -> exact gelu -> bf16 hi/lo in-place xh/xl
// grid (6, 512)
// ===========================================================================
__global__ void __launch_bounds__(256,1)
k_gemm_out(){
  extern __shared__ __align__(128) char smem[];
  const uint32_t sb = smem_u32(smem);
  const int tid = threadIdx.x;
  const int c0 = blockIdx.x * 128;
  const int bh = blockIdx.y, b = bh >> 3, h = bh & 7;
  const size_t Abase = ((size_t)b*C_ + c0) * N_ + (size_t)h*D_;
  float acc[16][4] = {};
  gemm_main(sb, tid, g_xh + Abase, g_xl + Abase, N_,
            g_kth + (size_t)bh*D_*D_, g_ktl + (size_t)bh*D_*D_, D_, 4, acc);
  const int wid = tid >> 5, lane = tid & 31;
  const int wm = (wid >> 2) * 64, wn = (wid & 3) * 32;
  const int tr = lane >> 2, tc = (lane & 3) * 2;
#pragma unroll
  for (int mi = 0; mi < 4; mi++)
#pragma unroll
    for (int ni = 0; ni < 4; ni++){
      float* a = acc[4*mi+ni];
      const int col = wn + ni*8 + tc;
      const size_t r0 = Abase + (size_t)(wm + mi*16 + tr) * N_ + col;
      const size_t r1 = r0 + 8*N_;
      uint32_t h0, l0;
      split2(gelu_exact(a[0]), gelu_exact(a[1]), h0, l0);
      *(uint32_t*)(g_xh + r0) = h0;
      *(uint32_t*)(g_xl + r0) = l0;
      split2(gelu_exact(a[2]), gelu_exact(a[3]), h0, l0);
      *(uint32_t*)(g_xh + r1) = h0;
      *(uint32_t*)(g_xl + r1) = l0;
    }
}

// ===========================================================================
// proj GEMM: out2 = gelu @ proj_w^T + pb; transposed fp32 write -> d_out [B,N,C]
// grid (8, 384)
// ===========================================================================
__global__ void __launch_bounds__(256,1)
k_gemm_proj(const __nv_bfloat16* __restrict__ Wh, const __nv_bfloat16* __restrict__ Wl,
            const float* __restrict__ pb, float* __restrict__ out){
  extern __shared__ __align__(128) char smem[];
  const uint32_t sb = smem_u32(smem);
  const int tid = threadIdx.x;
  const int n0 = blockIdx.x * 128, m0 = blockIdx.y * 128;
  float acc[16][4] = {};
  gemm_main(sb, tid, g_xh + (size_t)m0*N_, g_xl + (size_t)m0*N_, N_,
            Wh + (size_t)n0*N_, Wl + (size_t)n0*N_, N_, 32, acc);
  const int wid = tid >> 5, lane = tid & 31;
  const int wm = (wid >> 2) * 64, wn = (wid & 3) * 32;
  const int tr = lane >> 2, tc = (lane & 3) * 2;
  float* T = (float*)smem;
#pragma unroll
  for (int mi = 0; mi < 4; mi++)
#pragma unroll
    for (int ni = 0; ni < 4; ni++){
      float* a = acc[4*mi+ni];
      const int c = wn + ni*8 + tc;
      const float2 bv = *(const float2*)(pb + n0 + c);
      const int r = wm + mi*16 + tr;
      T[r*TS + c]     = a[0] + bv.x; T[r*TS + c + 1]     = a[1] + bv.y;
      T[(r+8)*TS + c] = a[2] + bv.x; T[(r+8)*TS + c + 1] = a[3] + bv.y;
    }
  __syncthreads();
  const int b = m0 / C_, c0 = m0 % C_;
  float* dst = out + ((size_t)b*N_ + n0) * C_ + c0;
#pragma unroll
  for (int it = 0; it < 4; it++){
    const int j = it*32 + (tid >> 3);
    const int mbase = (tid & 7) * 2;
#pragma unroll
    for (int p = 0; p < 8; p++){
      const int m = mbase + p*16;
      *(float2*)(dst + (size_t)j*C_ + m) = make_float2(T[m*TS + j], T[(m+1)*TS + j]);
    }
  }
}

// ===========================================================================
// x transpose fused with bf16 hi/lo split (no fp32 xt)
// ===========================================================================
__global__ void k_transpose_x(const float* __restrict__ in){
  __shared__ float t[32][33];
  const size_t zo = (size_t)blockIdx.z * C_ * N_;
  const int i0 = blockIdx.y*32, j0 = blockIdx.x*32;
  const float* ip = in + zo;
#pragma unroll
  for (int k = threadIdx.y; k < 32; k += 8)
    t[k][threadIdx.x] = ip[(size_t)(i0+k)*C_ + j0 + threadIdx.x];
  __syncthreads();
#pragma unroll
  for (int k = threadIdx.y; k < 32; k += 8){
    const size_t o = zo + (size_t)(j0+k)*N_ + i0 + threadIdx.x;
    const float v = t[threadIdx.x][k];
    uint32_t h;
    asm("cvt.rn.bf16x2.f32 %0, %1, %1;" : "=r"(h) : "f"(v));
    const float hv = __uint_as_float(h << 16);
    g_xh[o] = __ushort_as_bfloat16((unsigned short)(h & 0xffffu));
    float lv = v - hv;
    uint32_t l;
    asm("cvt.rn.bf16x2.f32 %0, %1, %1;" : "=r"(l) : "f"(lv));
    g_xl[o] = __ushort_as_bfloat16((unsigned short)(l & 0xffffu));
  }
}

// ---------------------------------------------------------------------------
// Launch: graph-capturable, allocation-free, deterministic.
// ---------------------------------------------------------------------------
extern "C" void kernel_launch(void* const* d_in, const int* in_sizes, int n_in,
                              void* d_out, int out_size){
  const float* x   = (const float*)d_in[0];
  const float* qkw = (const float*)d_in[1];
  const float* vw  = (const float*)d_in[2];
  const float* pw  = (const float*)d_in[3];
  const float* pb  = (const float*)d_in[4];
  const float* sc  = (const float*)d_in[5];
  float* out = (float*)d_out;

  __nv_bfloat16 *p_wh=nullptr, *p_wl=nullptr, *p_kTh=nullptr, *p_kTl=nullptr,
                *p_vTh=nullptr, *p_vTl=nullptr;
  cudaGetSymbolAddress((void**)&p_wh,  g_wh);
  cudaGetSymbolAddress((void**)&p_wl,  g_wl);
  cudaGetSymbolAddress((void**)&p_kTh, g_kTh);
  cudaGetSymbolAddress((void**)&p_kTl, g_kTl);
  cudaGetSymbolAddress((void**)&p_vTh, g_vTh);
  cudaGetSymbolAddress((void**)&p_vTl, g_vTl);

  cudaFuncSetAttribute(k_gemm_kv,  cudaFuncAttributeMaxDynamicSharedMemorySize, GSMEM);
  cudaFuncSetAttribute(k_gemm_kt,  cudaFuncAttributeMaxDynamicSharedMemorySize, GSMEM);
  cudaFuncSetAttribute(k_gemm_out, cudaFuncAttributeMaxDynamicSharedMemorySize, GSMEM);
  cudaFuncSetAttribute(k_gemm_proj,cudaFuncAttributeMaxDynamicSharedMemorySize, GSMEM);

  const size_t W2 = (size_t)N_*N_;

  // x -> xt bf16 hi/lo; weight splits
  k_transpose_x<<<dim3(24,32,64), dim3(32,8)>>>(x);
  k_split<<<1024, 256>>>((const float4*)qkw, (uint2*)(p_wh),      (uint2*)(p_wl),      (int)(W2/4));
  k_split<<<1024, 256>>>((const float4*)vw,  (uint2*)(p_wh+W2),   (uint2*)(p_wl+W2),   (int)(W2/4));
  k_split<<<1024, 256>>>((const float4*)pw,  (uint2*)(p_wh+2*W2), (uint2*)(p_wl+2*W2), (int)(W2/4));

  // k -> kT (+ norm partials), v -> vT
  k_gemm_kv<<<dim3(8,384), 256, GSMEM>>>(p_wh,    p_wl,    p_kTh, p_kTl, 1);
  k_gemm_kv<<<dim3(8,384), 256, GSMEM>>>(p_wh+W2, p_wl+W2, p_vTh, p_vTl, 0);
  k_reduce<<<1,1024>>>();

  // kt (HMMA, K=768) -> ktT bf16; out (HMMA, K=128) -> gelu in-place xh/xl
  k_gemm_kt<<<512, 256, GSMEM>>>(sc);
  k_gemm_out<<<dim3(6,512), 256, GSMEM>>>();

  // proj (HMMA, K=1024) + bias, transposed write direct to [B,N,C]
  k_gemm_proj<<<dim3(8,384), 256, GSMEM>>>(p_wh+2*W2, p_wl+2*W2, pb, out);
}